// round 16
// baseline (speedup 1.0000x reference)
#include <cuda_runtime.h>
#include <cuda_fp16.h>
#include <cstdint>

#define NPHEN 64
#define KSEL  32
#define BB    2048
#define DIN   1024
#define HIDD  2048
#define NPREP 64      // prep CTAs at head of grid
#define NFUSE 1024    // fused CTAs

// ---------------- scratch (device globals: allowed; no cudaMalloc) ----------
__device__ __align__(16) __half g_w1h[(size_t)NPHEN * HIDD * DIN];  // [p][h][d] fp16
__device__ __align__(16) __half g_xh[(size_t)BB * DIN];             // [b][d]    fp16
__device__ int g_t_prep;          // monotone ticket counters (epoch = ticket/N)
__device__ int g_t_fused;
__device__ int g_base;            // +1 per prep CTA when x/out ready
__device__ int g_pcnt[NPHEN];     // +1 per prep CTA per finished phenotype

// ---------------- helpers ---------------------------------------------------
__device__ __forceinline__ uint32_t smem_to_u32(const void* smem_ptr) {
    uint32_t addr;
    asm("{ .reg .u64 tmp; cvta.to.shared.u64 tmp, %1; cvt.u32.u64 %0, tmp; }"
        : "=r"(addr) : "l"(smem_ptr));
    return addr;
}
#define SMEM_SWIZZLE_128B(byte_offset) ((byte_offset) ^ (((byte_offset) >> 3) & 0x70))

// ---------------- subset handling (int32-vs-int64 robust) -------------------
__device__ __forceinline__ int detect64(const int* s) {
    int z = 1;
#pragma unroll
    for (int i = 0; i < 16; i++) z &= (s[2 * i + 1] == 0);
    return z;
}
__device__ __forceinline__ int get_subidx(const int* s, int k, int is64) {
    return is64 ? s[2 * k] : s[k];
}
__device__ __forceinline__ int find_rep(const int* s, int k, int is64) {
    int p = get_subidx(s, k, is64);
    for (int kk = 0; kk < k; ++kk)
        if (get_subidx(s, kk, is64) == p) return kk;
    return k;
}

// ---------------- fused-side constants ---------------------------------------
#define SM_STAGE 32768
#define SM_B1    98304
#define SM_W2    102400
#define SM_RED   106496
#define SM_TOT   107520
#define NIT      128   // 8 hid-tiles * 16 d-chunks

__device__ __forceinline__ void issue_chunk(uint32_t smem_base,
                                            const __half* __restrict__ Xh,
                                            const __half* __restrict__ Wh,
                                            int it, int h_base, int tid) {
    int nt = h_base + (it >> 4), dc = it & 15, stage = it % 3;
    uint32_t sA = smem_base + stage * SM_STAGE;
    uint32_t sB = sA + 16384;
    int d0 = dc * 64, h0 = nt * 128;
#pragma unroll
    for (int i = 0; i < 8; ++i) {
        int unit = tid + i * 128;
        int r = unit >> 3, q = unit & 7;
        uint32_t off = SMEM_SWIZZLE_128B((uint32_t)(r * 128 + q * 16));
        const __half* ga = Xh + (size_t)r * DIN + d0 + q * 8;
        const __half* gb = Wh + (size_t)(h0 + r) * DIN + d0 + q * 8;
        asm volatile("cp.async.cg.shared.global [%0], [%1], 16;" :: "r"(sA + off), "l"(ga));
        asm volatile("cp.async.cg.shared.global [%0], [%1], 16;" :: "r"(sB + off), "l"(gb));
    }
    asm volatile("cp.async.commit_group;" ::: "memory");
}

// ---------------- merged kernel ----------------------------------------------
__global__ void __launch_bounds__(128, 2)
mega_kernel(const float* __restrict__ x,
            const float* __restrict__ W1,
            const int* __restrict__ subset,
            const float* __restrict__ b1,
            const float* __restrict__ W2,
            const float* __restrict__ b2,
            float* __restrict__ out) {
    extern __shared__ char smem[];
    const uint32_t smem_base = smem_to_u32(smem);
    int tid = threadIdx.x;
    int bid = blockIdx.x;
    int is64 = detect64(subset);
    __shared__ int sh_ep;

    // ================= PREP PATH (bids 0..63) =================
    if (bid < NPREP) {
        int pid = bid;
        if (tid == 0) sh_ep = atomicAdd(&g_t_prep, 1) >> 6;   // 64 tickets/replay
        __syncthreads();
        int epoch = sh_ep; (void)epoch;

        // phase 1: x fp32->fp16 (8192 float4 per CTA) + out init (1024 per CTA)
        {
            const float4* src = reinterpret_cast<const float4*>(x);
            __half2* dst = reinterpret_cast<__half2*>(g_xh);
            int base = pid * 8192 + tid;
#pragma unroll 8
            for (int i = 0; i < 64; ++i) {
                int idx = base + i * 128;
                float4 v = src[idx];
                dst[2 * idx]     = __floats2half2_rn(v.x, v.y);
                dst[2 * idx + 1] = __floats2half2_rn(v.z, v.w);
            }
            int ob = pid * 1024 + tid;
#pragma unroll
            for (int i = 0; i < 8; ++i) {
                int idx = ob + i * 128;
                out[idx] = b2[get_subidx(subset, idx & (KSEL - 1), is64)];
            }
        }
        __threadfence();
        __syncthreads();
        if (tid == 0) atomicAdd(&g_base, 1);

        // phase 2: W1 transpose, phenotypes in k-order (matches fused need order)
        float (*t)[65] = reinterpret_cast<float(*)[65]>(smem);
        int tx = tid & 15, ty = tid >> 4;     // 16 x 8
        for (int k = 0; k < KSEL; ++k) {
            if (find_rep(subset, k, is64) != k) continue;
            int p = get_subidx(subset, k, is64);
#pragma unroll 1
            for (int j = 0; j < 8; ++j) {
                int tt = pid + 64 * j;                 // 0..511 tiles of 64x64
                int h0 = (tt & 31) * 64, d0 = (tt >> 5) * 64;
#pragma unroll
                for (int i = 0; i < 8; ++i) {
                    int dl = ty + i * 8;
                    float4 v = *reinterpret_cast<const float4*>(
                        &W1[((size_t)p * DIN + d0 + dl) * HIDD + h0 + 4 * tx]);
                    t[4 * tx + 0][dl] = v.x;
                    t[4 * tx + 1][dl] = v.y;
                    t[4 * tx + 2][dl] = v.z;
                    t[4 * tx + 3][dl] = v.w;
                }
                __syncthreads();
#pragma unroll
                for (int jj = 0; jj < 8; ++jj) {
                    int hl = ty + jj * 8;
                    __half2 h01 = __floats2half2_rn(t[hl][4 * tx],     t[hl][4 * tx + 1]);
                    __half2 h23 = __floats2half2_rn(t[hl][4 * tx + 2], t[hl][4 * tx + 3]);
                    uint2 uv;
                    uv.x = *reinterpret_cast<uint32_t*>(&h01);
                    uv.y = *reinterpret_cast<uint32_t*>(&h23);
                    *reinterpret_cast<uint2*>(
                        &g_w1h[((size_t)p * HIDD + h0 + hl) * DIN + d0 + 4 * tx]) = uv;
                }
                __syncthreads();
            }
            __threadfence();
            __syncthreads();
            if (tid == 0) atomicAdd(&g_pcnt[p], 1);
        }
        return;
    }

    // ================= FUSED PATH (bids 64..1087) =================
    if (tid == 0) sh_ep = atomicAdd(&g_t_fused, 1) >> 10;  // 1024 tickets/replay
    __syncthreads();
    int epoch = sh_ep;

    int fid = bid - NPREP;
    int bt = fid & 15;
    int y = fid >> 4;
    int k = y >> 1, half = y & 1;
    int h_base = half * 8;

    if (find_rep(subset, k, is64) != k) return;  // dup columns via atomicAdd below
    int p = get_subidx(subset, k, is64);

    // wait for prep: base (x/out) and this phenotype's W1
    if (tid == 0) {
        int tgt = NPREP * (epoch + 1);
        while (atomicAdd(&g_base, 0) < tgt) __nanosleep(200);
        while (atomicAdd(&g_pcnt[p], 0) < tgt) __nanosleep(200);
    }
    __syncthreads();

    int wid = tid >> 5, lid = tid & 31;
    int wm = wid >> 1, wn = wid & 1;
    int m0w = wm * 64, n0w = wn * 64;

    const __half* __restrict__ Xh = g_xh + (size_t)bt * 128 * DIN;
    const __half* __restrict__ Wh = g_w1h + (size_t)p * HIDD * DIN;
    float* b1s = reinterpret_cast<float*>(smem + SM_B1);
    float* w2s = reinterpret_cast<float*>(smem + SM_W2);

    float c[4][8][4];
#pragma unroll
    for (int mf = 0; mf < 4; ++mf)
#pragma unroll
        for (int nf = 0; nf < 8; ++nf)
#pragma unroll
            for (int j = 0; j < 4; ++j) c[mf][nf][j] = 0.0f;
    float accv[8] = {0.f, 0.f, 0.f, 0.f, 0.f, 0.f, 0.f, 0.f};

    uint32_t a[2][16], b[2][16];

    auto lda = [&](int buf, uint32_t sA, int s) {
        int kb = s * 32;
#pragma unroll
        for (int mf = 0; mf < 4; ++mf) {
            int row = m0w + mf * 16 + (lid & 15);
            int byt = kb + (lid >> 4) * 16;
            uint32_t addr = sA + SMEM_SWIZZLE_128B((uint32_t)(row * 128 + byt));
            asm volatile("ldmatrix.sync.aligned.m8n8.x4.shared.b16 {%0,%1,%2,%3}, [%4];"
                         : "=r"(a[buf][mf * 4]), "=r"(a[buf][mf * 4 + 1]),
                           "=r"(a[buf][mf * 4 + 2]), "=r"(a[buf][mf * 4 + 3])
                         : "r"(addr));
        }
    };
    auto ldb = [&](int buf, uint32_t sB, int s) {
        int kb = s * 32;
#pragma unroll
        for (int nq = 0; nq < 4; ++nq) {
            int row = n0w + nq * 16 + ((lid >> 4) * 8) + (lid & 7);
            int byt = kb + ((lid >> 3) & 1) * 16;
            uint32_t addr = sB + SMEM_SWIZZLE_128B((uint32_t)(row * 128 + byt));
            asm volatile("ldmatrix.sync.aligned.m8n8.x4.shared.b16 {%0,%1,%2,%3}, [%4];"
                         : "=r"(b[buf][nq * 4]), "=r"(b[buf][nq * 4 + 1]),
                           "=r"(b[buf][nq * 4 + 2]), "=r"(b[buf][nq * 4 + 3])
                         : "r"(addr));
        }
    };
    auto domma = [&](int buf) {
#pragma unroll
        for (int mf = 0; mf < 4; ++mf)
#pragma unroll
            for (int nf = 0; nf < 8; ++nf) {
                int bi = (nf >> 1) * 4 + (nf & 1) * 2;
                asm volatile(
                    "mma.sync.aligned.m16n8k16.row.col.f32.f16.f16.f32 "
                    "{%0,%1,%2,%3},{%4,%5,%6,%7},{%8,%9},{%0,%1,%2,%3};"
                    : "+f"(c[mf][nf][0]), "+f"(c[mf][nf][1]),
                      "+f"(c[mf][nf][2]), "+f"(c[mf][nf][3])
                    : "r"(a[buf][mf * 4]), "r"(a[buf][mf * 4 + 1]),
                      "r"(a[buf][mf * 4 + 2]), "r"(a[buf][mf * 4 + 3]),
                      "r"(b[buf][bi]), "r"(b[buf][bi + 1]));
            }
    };

    // prologue: 2 chunks in flight + whole-half b1/w2 preload
    issue_chunk(smem_base, Xh, Wh, 0, h_base, tid);
    issue_chunk(smem_base, Xh, Wh, 1, h_base, tid);
#pragma unroll
    for (int i = 0; i < 8; ++i) {
        int idx = tid + i * 128;
        b1s[idx] = b1[p * HIDD + half * 1024 + idx];
        w2s[idx] = W2[p * HIDD + half * 1024 + idx];
    }
    asm volatile("cp.async.wait_group 1;" ::: "memory");
    __syncthreads();

    for (int it = 0; it < NIT; ++it) {
        if (it + 2 < NIT) issue_chunk(smem_base, Xh, Wh, it + 2, h_base, tid);

        int stage = it % 3;
        uint32_t sA = smem_base + stage * SM_STAGE;
        uint32_t sB = sA + 16384;

        lda(0, sA, 0); ldb(0, sB, 0);
#pragma unroll
        for (int s = 0; s < 4; ++s) {
            if (s < 3) { lda((s + 1) & 1, sA, s + 1); ldb((s + 1) & 1, sB, s + 1); }
            domma(s & 1);
        }

        if ((it & 15) == 15) {
            int nt_off = (it >> 4) * 128;
            const float2* b1v = reinterpret_cast<const float2*>(b1s);
            const float2* w2v = reinterpret_cast<const float2*>(w2s);
#pragma unroll
            for (int mf = 0; mf < 4; ++mf)
#pragma unroll
                for (int nf = 0; nf < 8; ++nf) {
                    int col2 = (nt_off + n0w + nf * 8 + 2 * (lid & 3)) >> 1;
                    float2 bb = b1v[col2];
                    float2 ww = w2v[col2];
                    float v0 = c[mf][nf][0] + bb.x;
                    float v1 = c[mf][nf][1] + bb.y;
                    float v2 = c[mf][nf][2] + bb.x;
                    float v3 = c[mf][nf][3] + bb.y;
                    if (v0 > 0.f) accv[mf * 2]     = fmaf(v0, ww.x, accv[mf * 2]);
                    if (v1 > 0.f) accv[mf * 2]     = fmaf(v1, ww.y, accv[mf * 2]);
                    if (v2 > 0.f) accv[mf * 2 + 1] = fmaf(v2, ww.x, accv[mf * 2 + 1]);
                    if (v3 > 0.f) accv[mf * 2 + 1] = fmaf(v3, ww.y, accv[mf * 2 + 1]);
                    c[mf][nf][0] = c[mf][nf][1] = c[mf][nf][2] = c[mf][nf][3] = 0.0f;
                }
        }

        if (it + 2 < NIT)      asm volatile("cp.async.wait_group 1;" ::: "memory");
        else if (it + 1 < NIT) asm volatile("cp.async.wait_group 0;" ::: "memory");
        __syncthreads();
    }

    // ---- final reduction + atomic accumulate into all duplicate columns ----
    float* red = reinterpret_cast<float*>(smem + SM_RED);
#pragma unroll
    for (int j = 0; j < 8; ++j) {
        accv[j] += __shfl_xor_sync(0xffffffffu, accv[j], 1);
        accv[j] += __shfl_xor_sync(0xffffffffu, accv[j], 2);
    }
    if ((lid & 3) == 0) {
        int g = lid >> 2;
#pragma unroll
        for (int mf = 0; mf < 4; ++mf) {
            red[wn * 128 + m0w + mf * 16 + g]     = accv[mf * 2];
            red[wn * 128 + m0w + mf * 16 + g + 8] = accv[mf * 2 + 1];
        }
    }
    __syncthreads();
    {
        int b = bt * 128 + tid;
        float v = red[tid] + red[128 + tid];
#pragma unroll
        for (int kk = 0; kk < KSEL; ++kk)
            if (get_subidx(subset, kk, is64) == p)
                atomicAdd(&out[(size_t)b * KSEL + kk], v);
    }
}

// ---------------- launch ----------------------------------------------------
extern "C" void kernel_launch(void* const* d_in, const int* in_sizes, int n_in,
                              void* d_out, int out_size) {
    const float* x      = (const float*)d_in[0];
    const int*   subset = (const int*)d_in[1];
    const float* W1     = (const float*)d_in[2];
    const float* b1     = (const float*)d_in[3];
    const float* W2     = (const float*)d_in[4];
    const float* b2     = (const float*)d_in[5];
    float* out = (float*)d_out;

    cudaFuncSetAttribute(mega_kernel,
                         cudaFuncAttributeMaxDynamicSharedMemorySize, SM_TOT);

    mega_kernel<<<NPREP + NFUSE, 128, SM_TOT>>>(x, W1, subset, b1, W2, b2, out);
}

// round 17
// speedup vs baseline: 1.3548x; 1.3548x over previous
#include <cuda_runtime.h>
#include <cuda_fp16.h>
#include <cstdint>

#define NPHEN 64
#define KSEL  32
#define BB    2048
#define DIN   1024
#define HIDD  2048

// ---------------- scratch (device globals: allowed; no cudaMalloc) ----------
__device__ __align__(16) __half g_w1h[(size_t)NPHEN * HIDD * DIN];  // [p][h][d] fp16
__device__ __align__(16) __half g_xh[(size_t)BB * DIN];             // [b][d]    fp16

// ---------------- helpers ---------------------------------------------------
__device__ __forceinline__ uint32_t smem_to_u32(const void* smem_ptr) {
    uint32_t addr;
    asm("{ .reg .u64 tmp; cvta.to.shared.u64 tmp, %1; cvt.u32.u64 %0, tmp; }"
        : "=r"(addr) : "l"(smem_ptr));
    return addr;
}
#define SMEM_SWIZZLE_128B(byte_offset) ((byte_offset) ^ (((byte_offset) >> 3) & 0x70))

// ---------------- subset handling (int32-vs-int64 robust) -------------------
__device__ __forceinline__ int detect64(const int* s) {
    int z = 1;
#pragma unroll
    for (int i = 0; i < 16; i++) z &= (s[2 * i + 1] == 0);
    return z;
}
__device__ __forceinline__ int get_subidx(const int* s, int k, int is64) {
    return is64 ? s[2 * k] : s[k];
}
__device__ __forceinline__ int find_rep(const int* s, int k, int is64) {
    int p = get_subidx(s, k, is64);
    for (int kk = 0; kk < k; ++kk)
        if (get_subidx(s, kk, is64) == p) return kk;
    return k;
}

// ---------------- prep kernel ------------------------------------------------
// grid (32, 16, 34), block 256.
//   z in [0,32): transpose+convert W1 for k=z (deduped); tile 64(h) x 64(d)
//   z == 32:     x fp32 -> fp16  (512 blocks x 4096 floats)
//   z == 33:     out init = b2[p_k]
__global__ void __launch_bounds__(256)
prep_kernel(const float* __restrict__ x,
            const float* __restrict__ W1,
            const int* __restrict__ subset,
            const float* __restrict__ b2,
            float* __restrict__ out) {
    int tid = threadIdx.x;
    if (blockIdx.z == 32) {
        int ib = (blockIdx.y * 32 + blockIdx.x) * 1024;   // float4 base
        const float4* src = reinterpret_cast<const float4*>(x);
        __half2* dst = reinterpret_cast<__half2*>(g_xh);
#pragma unroll
        for (int u = 0; u < 4; ++u) {
            int i = ib + u * 256 + tid;
            float4 v = src[i];
            dst[2 * i]     = __floats2half2_rn(v.x, v.y);
            dst[2 * i + 1] = __floats2half2_rn(v.z, v.w);
        }
        return;
    }
    if (blockIdx.z == 33) {
        int idx = (blockIdx.y * 32 + blockIdx.x) * 256 + tid;
        if (idx < BB * KSEL) {
            int is64 = detect64(subset);
            out[idx] = b2[get_subidx(subset, idx & (KSEL - 1), is64)];
        }
        return;
    }
    int k = blockIdx.z;
    int is64 = detect64(subset);
    if (find_rep(subset, k, is64) != k) return;  // dedup
    int p = get_subidx(subset, k, is64);
    int h0 = blockIdx.x * 64, d0 = blockIdx.y * 64;

    __shared__ float t[64][65];                  // [hl][dl], 2-way max conflicts
    // read: 64 d-rows x 16 float4 of h (fully coalesced 128B per 16 lanes)
#pragma unroll
    for (int i = 0; i < 4; ++i) {
        int unit = i * 256 + tid;
        int dl = unit >> 4, q = unit & 15;
        float4 v = *reinterpret_cast<const float4*>(
            &W1[((size_t)p * DIN + d0 + dl) * HIDD + h0 + 4 * q]);
        t[4 * q + 0][dl] = v.x;
        t[4 * q + 1][dl] = v.y;
        t[4 * q + 2][dl] = v.z;
        t[4 * q + 3][dl] = v.w;
    }
    __syncthreads();
    // write: 64 h-rows x 16 uint2 of d (8B/lane, 128B per 16 lanes)
#pragma unroll
    for (int j = 0; j < 4; ++j) {
        int unit = j * 256 + tid;
        int hl = unit >> 4, q = unit & 15;
        __half2 h01 = __floats2half2_rn(t[hl][4 * q],     t[hl][4 * q + 1]);
        __half2 h23 = __floats2half2_rn(t[hl][4 * q + 2], t[hl][4 * q + 3]);
        uint2 uv;
        uv.x = *reinterpret_cast<uint32_t*>(&h01);
        uv.y = *reinterpret_cast<uint32_t*>(&h23);
        *reinterpret_cast<uint2*>(
            &g_w1h[((size_t)p * HIDD + h0 + hl) * DIN + d0 + 4 * q]) = uv;
    }
}

// ---------------- main fused kernel (R11/R15 config — best measured) ---------
// grid (16, 64): y = k*2+half; CTA does half of HID (8 tiles of 128).
// 128 threads = 4 warps (2x2), warp tile 64x64. BK=64, 3-stage cp.async.
#define SM_STAGE 32768
#define SM_B1    98304
#define SM_W2    102400
#define SM_RED   106496
#define SM_TOT   107520
#define NIT      128   // 8 hid-tiles * 16 d-chunks

__device__ __forceinline__ void issue_chunk(uint32_t smem_base,
                                            const __half* __restrict__ Xh,
                                            const __half* __restrict__ Wh,
                                            int it, int h_base, int tid) {
    int nt = h_base + (it >> 4), dc = it & 15, stage = it % 3;
    uint32_t sA = smem_base + stage * SM_STAGE;
    uint32_t sB = sA + 16384;
    int d0 = dc * 64, h0 = nt * 128;
#pragma unroll
    for (int i = 0; i < 8; ++i) {
        int unit = tid + i * 128;
        int r = unit >> 3, q = unit & 7;
        uint32_t off = SMEM_SWIZZLE_128B((uint32_t)(r * 128 + q * 16));
        const __half* ga = Xh + (size_t)r * DIN + d0 + q * 8;
        const __half* gb = Wh + (size_t)(h0 + r) * DIN + d0 + q * 8;
        asm volatile("cp.async.cg.shared.global [%0], [%1], 16;" :: "r"(sA + off), "l"(ga));
        asm volatile("cp.async.cg.shared.global [%0], [%1], 16;" :: "r"(sB + off), "l"(gb));
    }
    asm volatile("cp.async.commit_group;" ::: "memory");
}

__global__ void __launch_bounds__(128, 2)
fused_main_kernel(const int* __restrict__ subset,
                  const float* __restrict__ b1,
                  const float* __restrict__ W2,
                  float* __restrict__ out) {
    extern __shared__ char smem[];
    const uint32_t smem_base = smem_to_u32(smem);
    int tid = threadIdx.x, wid = tid >> 5, lid = tid & 31;
    int wm = wid >> 1, wn = wid & 1;       // 2 x 2 warp grid, 64x64 tiles
    int m0w = wm * 64, n0w = wn * 64;
    int bt = blockIdx.x;
    int k = blockIdx.y >> 1, half = blockIdx.y & 1;
    int h_base = half * 8;

    int is64 = detect64(subset);
    if (find_rep(subset, k, is64) != k) return;  // dup columns via atomicAdd below
    int p = get_subidx(subset, k, is64);

    const __half* __restrict__ Xh = g_xh + (size_t)bt * 128 * DIN;
    const __half* __restrict__ Wh = g_w1h + (size_t)p * HIDD * DIN;
    float* b1s = reinterpret_cast<float*>(smem + SM_B1);   // 1024 floats
    float* w2s = reinterpret_cast<float*>(smem + SM_W2);   // 1024 floats

    float c[4][8][4];
#pragma unroll
    for (int mf = 0; mf < 4; ++mf)
#pragma unroll
        for (int nf = 0; nf < 8; ++nf)
#pragma unroll
            for (int j = 0; j < 4; ++j) c[mf][nf][j] = 0.0f;
    float accv[8] = {0.f, 0.f, 0.f, 0.f, 0.f, 0.f, 0.f, 0.f};

    uint32_t a[2][16], b[2][16];

    auto lda = [&](int buf, uint32_t sA, int s) {
        int kb = s * 32;
#pragma unroll
        for (int mf = 0; mf < 4; ++mf) {
            int row = m0w + mf * 16 + (lid & 15);
            int byt = kb + (lid >> 4) * 16;
            uint32_t addr = sA + SMEM_SWIZZLE_128B((uint32_t)(row * 128 + byt));
            asm volatile("ldmatrix.sync.aligned.m8n8.x4.shared.b16 {%0,%1,%2,%3}, [%4];"
                         : "=r"(a[buf][mf * 4]), "=r"(a[buf][mf * 4 + 1]),
                           "=r"(a[buf][mf * 4 + 2]), "=r"(a[buf][mf * 4 + 3])
                         : "r"(addr));
        }
    };
    auto ldb = [&](int buf, uint32_t sB, int s) {
        int kb = s * 32;
#pragma unroll
        for (int nq = 0; nq < 4; ++nq) {
            int row = n0w + nq * 16 + ((lid >> 4) * 8) + (lid & 7);
            int byt = kb + ((lid >> 3) & 1) * 16;
            uint32_t addr = sB + SMEM_SWIZZLE_128B((uint32_t)(row * 128 + byt));
            asm volatile("ldmatrix.sync.aligned.m8n8.x4.shared.b16 {%0,%1,%2,%3}, [%4];"
                         : "=r"(b[buf][nq * 4]), "=r"(b[buf][nq * 4 + 1]),
                           "=r"(b[buf][nq * 4 + 2]), "=r"(b[buf][nq * 4 + 3])
                         : "r"(addr));
        }
    };
    auto domma = [&](int buf) {
#pragma unroll
        for (int mf = 0; mf < 4; ++mf)
#pragma unroll
            for (int nf = 0; nf < 8; ++nf) {
                int bi = (nf >> 1) * 4 + (nf & 1) * 2;
                asm volatile(
                    "mma.sync.aligned.m16n8k16.row.col.f32.f16.f16.f32 "
                    "{%0,%1,%2,%3},{%4,%5,%6,%7},{%8,%9},{%0,%1,%2,%3};"
                    : "+f"(c[mf][nf][0]), "+f"(c[mf][nf][1]),
                      "+f"(c[mf][nf][2]), "+f"(c[mf][nf][3])
                    : "r"(a[buf][mf * 4]), "r"(a[buf][mf * 4 + 1]),
                      "r"(a[buf][mf * 4 + 2]), "r"(a[buf][mf * 4 + 3]),
                      "r"(b[buf][bi]), "r"(b[buf][bi + 1]));
            }
    };

    // prologue: 2 chunks in flight + whole-half b1/w2 preload
    issue_chunk(smem_base, Xh, Wh, 0, h_base, tid);
    issue_chunk(smem_base, Xh, Wh, 1, h_base, tid);
#pragma unroll
    for (int i = 0; i < 8; ++i) {
        int idx = tid + i * 128;
        b1s[idx] = b1[p * HIDD + half * 1024 + idx];
        w2s[idx] = W2[p * HIDD + half * 1024 + idx];
    }
    asm volatile("cp.async.wait_group 1;" ::: "memory");   // chunk 0 ready
    __syncthreads();

    for (int it = 0; it < NIT; ++it) {
        if (it + 2 < NIT) issue_chunk(smem_base, Xh, Wh, it + 2, h_base, tid);

        int stage = it % 3;
        uint32_t sA = smem_base + stage * SM_STAGE;
        uint32_t sB = sA + 16384;

        lda(0, sA, 0); ldb(0, sB, 0);
#pragma unroll
        for (int s = 0; s < 4; ++s) {
            if (s < 3) { lda((s + 1) & 1, sA, s + 1); ldb((s + 1) & 1, sB, s + 1); }
            domma(s & 1);
        }

        // ---- fused epilogue at end of each hid-tile ----
        if ((it & 15) == 15) {
            int nt_off = (it >> 4) * 128;
            const float2* b1v = reinterpret_cast<const float2*>(b1s);
            const float2* w2v = reinterpret_cast<const float2*>(w2s);
#pragma unroll
            for (int mf = 0; mf < 4; ++mf)
#pragma unroll
                for (int nf = 0; nf < 8; ++nf) {
                    int col2 = (nt_off + n0w + nf * 8 + 2 * (lid & 3)) >> 1;
                    float2 bb = b1v[col2];
                    float2 ww = w2v[col2];
                    float v0 = c[mf][nf][0] + bb.x;
                    float v1 = c[mf][nf][1] + bb.y;
                    float v2 = c[mf][nf][2] + bb.x;
                    float v3 = c[mf][nf][3] + bb.y;
                    if (v0 > 0.f) accv[mf * 2]     = fmaf(v0, ww.x, accv[mf * 2]);
                    if (v1 > 0.f) accv[mf * 2]     = fmaf(v1, ww.y, accv[mf * 2]);
                    if (v2 > 0.f) accv[mf * 2 + 1] = fmaf(v2, ww.x, accv[mf * 2 + 1]);
                    if (v3 > 0.f) accv[mf * 2 + 1] = fmaf(v3, ww.y, accv[mf * 2 + 1]);
                    c[mf][nf][0] = c[mf][nf][1] = c[mf][nf][2] = c[mf][nf][3] = 0.0f;
                }
        }

        if (it + 2 < NIT)      asm volatile("cp.async.wait_group 1;" ::: "memory");
        else if (it + 1 < NIT) asm volatile("cp.async.wait_group 0;" ::: "memory");
        __syncthreads();
    }

    // ---- final reduction + atomic accumulate into all duplicate columns ----
    float* red = reinterpret_cast<float*>(smem + SM_RED);  // [2 wn][128 rows]
#pragma unroll
    for (int j = 0; j < 8; ++j) {   // reduce over the 4 col-lanes of each row
        accv[j] += __shfl_xor_sync(0xffffffffu, accv[j], 1);
        accv[j] += __shfl_xor_sync(0xffffffffu, accv[j], 2);
    }
    if ((lid & 3) == 0) {
        int g = lid >> 2;            // 0..7
#pragma unroll
        for (int mf = 0; mf < 4; ++mf) {
            red[wn * 128 + m0w + mf * 16 + g]     = accv[mf * 2];
            red[wn * 128 + m0w + mf * 16 + g + 8] = accv[mf * 2 + 1];
        }
    }
    __syncthreads();
    {
        int b = bt * 128 + tid;
        float v = red[tid] + red[128 + tid];
#pragma unroll
        for (int kk = 0; kk < KSEL; ++kk)
            if (get_subidx(subset, kk, is64) == p)
                atomicAdd(&out[(size_t)b * KSEL + kk], v);
    }
}

// ---------------- launch ----------------------------------------------------
extern "C" void kernel_launch(void* const* d_in, const int* in_sizes, int n_in,
                              void* d_out, int out_size) {
    const float* x      = (const float*)d_in[0];
    const int*   subset = (const int*)d_in[1];
    const float* W1     = (const float*)d_in[2];
    const float* b1     = (const float*)d_in[3];
    const float* W2     = (const float*)d_in[4];
    const float* b2     = (const float*)d_in[5];
    float* out = (float*)d_out;

    cudaFuncSetAttribute(fused_main_kernel,
                         cudaFuncAttributeMaxDynamicSharedMemorySize, SM_TOT);

    prep_kernel<<<dim3(32, 16, 34), 256>>>(x, W1, subset, b2, out);
    fused_main_kernel<<<dim3(16, 64), 128, SM_TOT>>>(subset, b1, W2, out);
}